// round 14
// baseline (speedup 1.0000x reference)
#include <cuda_runtime.h>
#include <cstdint>

#define NN 256
#define KK 64
#define TT 128
#define FF 64
#define TN 8
#define TK 16
#define TC2 4
#define GRID 128
#define NTHR 512
#define SMEM_BYTES (2 * 2 * 1536 * 16)   // 2 groups x 2 stages x 1536 float4 = 96KB

typedef unsigned long long u64;
typedef unsigned int u32;

// ---------------- scratch (no allocations allowed) ----------------
__device__ float g_dist[NN * KK];
__device__ float g_qpart[GRID * KK];
__device__ float g_lossb[GRID];
__device__ int g_c1, g_f1, g_c2, g_f2, g_c3;   // zero-init sync state

__device__ __forceinline__ u64 ffma2(u64 a, u64 b, u64 c) {
    u64 d;
    asm("fma.rn.f32x2 %0, %1, %2, %3;" : "=l"(d) : "l"(a), "l"(b), "l"(c));
    return d;
}
__device__ __forceinline__ float2 upk(u64 v) {
    float2 r;
    asm("mov.b64 {%0, %1}, %2;" : "=f"(r.x), "=f"(r.y) : "l"(v));
    return r;
}
__device__ __forceinline__ float fsqrt_approx(float x) {
    float r;
    asm("sqrt.approx.f32 %0, %1;" : "=f"(r) : "f"(x));
    return r;
}
__device__ __forceinline__ void bar_group(int id) {
    asm volatile("bar.sync %0, 256;" :: "r"(id) : "memory");
}
__device__ __forceinline__ void cp16(u32 s, const float4* g) {
    asm volatile("cp.async.cg.shared.global [%0], [%1], 16;" :: "r"(s), "l"(g));
}
__device__ __forceinline__ void cp_commit() {
    asm volatile("cp.async.commit_group;" ::: "memory");
}
template <int N>
__device__ __forceinline__ void cp_wait() {
    asm volatile("cp.async.wait_group %0;" :: "n"(N) : "memory");
}

// device-wide barrier: all GRID blocks co-resident (128 blocks, 1/SM)
__device__ __forceinline__ void gsync(int* cnt, int* flag) {
    __syncthreads();
    if (threadIdx.x == 0) {
        __threadfence();
        if (atomicAdd(cnt, 1) == GRID - 1) {
            atomicExch(flag, 1);
        } else {
            while (atomicAdd(flag, 0) == 0) { __nanosleep(32); }
        }
    }
    __syncthreads();
}

extern __shared__ float4 smem4[];   // [group][stage][1536]: xs [0,512), cs [512,1536)

__global__ void __launch_bounds__(NTHR, 1)
soft_kmeans_mega(const float* __restrict__ x, const float* __restrict__ c,
                 float* __restrict__ out, int out_size) {
    const int tid = threadIdx.x;
    const int b   = blockIdx.x;
    const int g   = tid >> 8;              // warp-group 0/1 (T halves), 256 thr each
    const int wt  = tid & 255;

    // ===== Phase 1: distance tile (8n x 16k), T split, 2-stage pipeline =====
    {
        const int fg = wt & 15;            // f-group of 4 floats
        const int pg = wt >> 4;            // 0..15
        const int ni = pg & 1;             // 2 n-subtiles of 4
        const int ki = pg >> 1;            // 8 k-subtiles of 2
        const int n0 = (b >> 2) * TN;
        const int k0 = (b & 3) * TK;

        const float4* __restrict__ xg = (const float4*)x;  // (n*TT+t)*16+f4
        const float4* __restrict__ cg = (const float4*)c;

        const u32 base_s = (u32)__cvta_generic_to_shared(smem4);
        const u32 g_s    = base_s + g * 2 * 24576;          // group's 2 stages

        u64 acc[4][2][2];                  // 4n x 2k x 4f
        u64 x2a[4][2], c2a[2][2];
#pragma unroll
        for (int i = 0; i < 4; i++) {
            x2a[i][0] = 0ull; x2a[i][1] = 0ull;
#pragma unroll
            for (int j = 0; j < 2; j++) { acc[i][j][0] = 0ull; acc[i][j][1] = 0ull; }
        }
        c2a[0][0] = c2a[0][1] = c2a[1][0] = c2a[1][1] = 0ull;

        // -------- issue loads for chunk ch into stage st --------
        auto issue_chunk = [&](int ch, int st) {
            const int t0 = g * 64 + ch * TC2;
            const u32 xs_s = g_s + st * 24576;
            const u32 cs_s = xs_s + 512 * 16;
            // x tile: 8n*4t*16f4 = 512 float4, 2 per thread
#pragma unroll
            for (int i = 0; i < 2; i++) {
                int idx   = wt + i * 256;
                int nn    = idx >> 6;
                int inner = idx & 63;      // tt*16 + f4
                cp16(xs_s + idx * 16,
                     xg + ((n0 + nn) * TT + t0 + (inner >> 4)) * 16 + (inner & 15));
            }
            // c tile: 16k*4t*16f4 = 1024 float4, 4 per thread
#pragma unroll
            for (int i = 0; i < 4; i++) {
                int idx   = wt + i * 256;
                int kk    = idx >> 6;
                int inner = idx & 63;
                cp16(cs_s + idx * 16,
                     cg + ((k0 + kk) * TT + t0 + (inner >> 4)) * 16 + (inner & 15));
            }
            cp_commit();
        };

        issue_chunk(0, 0);                  // prologue

#pragma unroll 2
        for (int ch = 0; ch < 16; ch++) {
            const int st = ch & 1;
            bar_group(1 + g);               // compute of ch-1 done -> stage st^1 free
            if (ch < 15) {
                issue_chunk(ch + 1, st ^ 1);
                cp_wait<1>();               // chunk ch landed (only ch+1 pending)
            } else {
                cp_wait<0>();
            }
            bar_group(1 + g);               // chunk ch visible group-wide

            const ulonglong2* xsu = (const ulonglong2*)(smem4 + (g * 2 + st) * 1536);
            const ulonglong2* csu = xsu + 512;
#pragma unroll
            for (int tt = 0; tt < TC2; tt++) {
                ulonglong2 xv[4], cv[2];
#pragma unroll
                for (int i = 0; i < 4; i++)
                    xv[i] = xsu[((ni * 4 + i) * TC2 + tt) * 16 + fg];
#pragma unroll
                for (int j = 0; j < 2; j++)
                    cv[j] = csu[((ki * 2 + j) * TC2 + tt) * 16 + fg];
#pragma unroll
                for (int i = 0; i < 4; i++) {
                    x2a[i][0] = ffma2(xv[i].x, xv[i].x, x2a[i][0]);
                    x2a[i][1] = ffma2(xv[i].y, xv[i].y, x2a[i][1]);
                }
#pragma unroll
                for (int j = 0; j < 2; j++) {
                    c2a[j][0] = ffma2(cv[j].x, cv[j].x, c2a[j][0]);
                    c2a[j][1] = ffma2(cv[j].y, cv[j].y, c2a[j][1]);
                }
#pragma unroll
                for (int i = 0; i < 4; i++)
#pragma unroll
                    for (int j = 0; j < 2; j++) {
                        acc[i][j][0] = ffma2(xv[i].x, cv[j].x, acc[i][j][0]);
                        acc[i][j][1] = ffma2(xv[i].y, cv[j].y, acc[i][j][1]);
                    }
            }
        }

        // -------- unpack into va[48]: acc(32) | x2(16... packed) --------
        float va[48];                      // acc 32 | x2 16-? layout: acc 0..31, x2 32..39? no:
        // acc: 4n*2k*4f = 32 floats [0,32); x2: 4n*4f = 16 [32,48)? c2: 2k*4f = 8 -> need 56
        float vb[8];                       // c2 separate (8 floats)
#pragma unroll
        for (int i = 0; i < 4; i++)
#pragma unroll
            for (int j = 0; j < 2; j++) {
                float2 a0 = upk(acc[i][j][0]), a1 = upk(acc[i][j][1]);
                int p = (i * 2 + j) * 4;
                va[p] = a0.x; va[p + 1] = a0.y; va[p + 2] = a1.x; va[p + 3] = a1.y;
            }
#pragma unroll
        for (int i = 0; i < 4; i++) {
            float2 a0 = upk(x2a[i][0]), a1 = upk(x2a[i][1]);
            va[32 + i * 4] = a0.x; va[32 + i * 4 + 1] = a0.y;
            va[32 + i * 4 + 2] = a1.x; va[32 + i * 4 + 3] = a1.y;
        }
#pragma unroll
        for (int j = 0; j < 2; j++) {
            float2 a0 = upk(c2a[j][0]), a1 = upk(c2a[j][1]);
            vb[j * 4] = a0.x; vb[j * 4 + 1] = a0.y;
            vb[j * 4 + 2] = a1.x; vb[j * 4 + 3] = a1.y;
        }

        // -------- combine group 1 partials into group 0 (conflict-free) ----
        float* sall = (float*)smem4;       // 56*256 floats = 56KB < 96KB
        __syncthreads();
        if (g == 1) {
#pragma unroll
            for (int j = 0; j < 48; j++) sall[j * 256 + wt] = va[j];
#pragma unroll
            for (int j = 0; j < 8; j++)  sall[(48 + j) * 256 + wt] = vb[j];
        }
        __syncthreads();
        if (g == 0) {
#pragma unroll
            for (int j = 0; j < 48; j++) va[j] += sall[j * 256 + wt];
#pragma unroll
            for (int j = 0; j < 8; j++)  vb[j] += sall[(48 + j) * 256 + wt];

            // epilogue: d2 = max(x2 + c2 - 2*xc, 0); dist = sum_f sqrt(d2)
#pragma unroll
            for (int i = 0; i < 4; i++) {
#pragma unroll
                for (int j = 0; j < 2; j++) {
                    int p = (i * 2 + j) * 4;
                    float d0 = fmaxf(va[32 + i * 4 + 0] + vb[j * 4 + 0] - 2.0f * va[p + 0], 0.0f);
                    float d1 = fmaxf(va[32 + i * 4 + 1] + vb[j * 4 + 1] - 2.0f * va[p + 1], 0.0f);
                    float d2 = fmaxf(va[32 + i * 4 + 2] + vb[j * 4 + 2] - 2.0f * va[p + 2], 0.0f);
                    float d3 = fmaxf(va[32 + i * 4 + 3] + vb[j * 4 + 3] - 2.0f * va[p + 3], 0.0f);
                    float part = fsqrt_approx(d0) + fsqrt_approx(d1) +
                                 fsqrt_approx(d2) + fsqrt_approx(d3);
#pragma unroll
                    for (int off = 8; off; off >>= 1)
                        part += __shfl_down_sync(0xffffffffu, part, off, 16);
                    if (fg == 0)
                        g_dist[(n0 + ni * 4 + i) * KK + (k0 + ki * 2 + j)] = part;
                }
            }
        }
    }

    gsync(&g_c1, &g_f1);   // g_dist complete everywhere

    float* s_tmp  = (float*)smem4;         // 512 floats
    float* s_red  = (float*)smem4 + 512;   // 8 floats
    int*   s_last = (int*)((float*)smem4 + 526);

    // ================= Phase 2: q = softmax_k(1/(1+d^2)), rows 2b,2b+1 =====
    const int rloc = (tid >> 6) & 1;
    const int k    = tid & 63;
    const int n    = b * 2 + rloc;
    const int w    = tid >> 5;
    const int lane = tid & 31;
    const bool act = tid < 128;

    float q = 0.0f, e = 0.0f;
    if (act) {
        float d  = g_dist[n * KK + k];
        float q1 = 1.0f / (1.0f + d * d);   // alpha=1 -> exponent 1
        float m = q1;
#pragma unroll
        for (int o = 16; o; o >>= 1) m = fmaxf(m, __shfl_xor_sync(0xffffffffu, m, o));
        if (lane == 0) s_red[w] = m;
        e = q1;                             // stash q1
    }
    __syncthreads();
    if (act) {
        float m = fmaxf(s_red[rloc * 2], s_red[rloc * 2 + 1]);
        e = expf(e - m);
        float s = e;
#pragma unroll
        for (int o = 16; o; o >>= 1) s += __shfl_xor_sync(0xffffffffu, s, o);
        if (lane == 0) s_red[4 + w] = s;
    }
    __syncthreads();
    if (act) {
        float s = s_red[4 + rloc * 2] + s_red[4 + rloc * 2 + 1];
        q = e / s;
        out[n * KK + k] = q;
        s_tmp[tid] = q;
    }
    __syncthreads();
    if (tid < 64) g_qpart[b * KK + tid] = s_tmp[tid] + s_tmp[tid + 64];

    gsync(&g_c2, &g_f2);   // all qpart written

    // ================= Phase 3: qsum, p, loss =================
    {
        // qsum[k] = sum over 128 blocks; 8-way split over thread eighths
        const int eighth = tid >> 6;        // 0..7
        const int kq = tid & 63;
        float part = 0.0f;
#pragma unroll 8
        for (int bb = 0; bb < 16; bb++)
            part += g_qpart[(eighth * 16 + bb) * KK + kq];
        s_tmp[tid] = part;
        __syncthreads();
        float t = 0.0f;
        if (act) {
            float qsum = 0.0f;
#pragma unroll
            for (int m8 = 0; m8 < 8; m8++) qsum += s_tmp[m8 * 64 + k];
            t = (q * q) / qsum;
            float m = t;
#pragma unroll
            for (int o = 16; o; o >>= 1) m = fmaxf(m, __shfl_xor_sync(0xffffffffu, m, o));
            if (lane == 0) s_red[w] = m;
        }
        __syncthreads();
        if (act) {
            float m = fmaxf(s_red[rloc * 2], s_red[rloc * 2 + 1]);
            e = expf(t - m);
            float s = e;
#pragma unroll
            for (int o = 16; o; o >>= 1) s += __shfl_xor_sync(0xffffffffu, s, o);
            if (lane == 0) s_red[4 + w] = s;
        }
        __syncthreads();
        if (act) {
            float s = s_red[4 + rloc * 2] + s_red[4 + rloc * 2 + 1];
            float p = e / s;
            float term = q * (logf(q) - p);
#pragma unroll
            for (int o = 16; o; o >>= 1) term += __shfl_xor_sync(0xffffffffu, term, o);
            if (lane == 0) s_red[w] = term;
        }
        __syncthreads();
        if (tid == 0)
            g_lossb[b] = s_red[0] + s_red[1] + s_red[2] + s_red[3];
        __syncthreads();
    }

    // ================= Phase 4: last block finalizes loss, resets sync =====
    if (tid == 0) {
        __threadfence();
        int old = atomicAdd(&g_c3, 1);
        *s_last = (old == GRID - 1) ? 1 : 0;
    }
    __syncthreads();
    if (*s_last) {
        if (tid < 128) s_tmp[tid] = g_lossb[tid];
        __syncthreads();
#pragma unroll
        for (int o = 64; o; o >>= 1) {
            if (tid < o) s_tmp[tid] += s_tmp[tid + o];
            __syncthreads();
        }
        if (tid == 0) {
            if (out_size > NN * KK) out[NN * KK] = s_tmp[0] / (float)NN;
            atomicExch(&g_c1, 0); atomicExch(&g_f1, 0);
            atomicExch(&g_c2, 0); atomicExch(&g_f2, 0);
            atomicExch(&g_c3, 0);
            __threadfence();
        }
    }
}

extern "C" void kernel_launch(void* const* d_in, const int* in_sizes, int n_in,
                              void* d_out, int out_size) {
    const float* x = (const float*)d_in[0];   // inputs  (N,T,F)
    const float* c = (const float*)d_in[1];   // clusters(K,T,F)
    float* out = (float*)d_out;

    cudaFuncSetAttribute(soft_kmeans_mega,
                         cudaFuncAttributeMaxDynamicSharedMemorySize, SMEM_BYTES);
    soft_kmeans_mega<<<GRID, NTHR, SMEM_BYTES>>>(x, c, out, out_size);
}

// round 15
// speedup vs baseline: 1.1629x; 1.1629x over previous
#include <cuda_runtime.h>
#include <cuda_bf16.h>
#include <cstdint>

#define NN 256
#define KK 64
#define TT 128
#define FF 64
#define TN 8
#define TK 16
#define GRID 128
#define NTHR 256
#define STAGE_B 12288                     // bytes per stage: x 4KB + c 8KB (bf16)
#define SMEM_BYTES (4 * 2 * STAGE_B)      // 4 T-groups x 2 stages = 96KB

typedef unsigned long long u64;
typedef unsigned int u32;

// ---------------- scratch (no allocations allowed) ----------------
__device__ __nv_bfloat16 g_xb[NN * TT * FF];   // 4MB bf16 copy of x
__device__ __nv_bfloat16 g_cb[KK * TT * FF];   // 1MB bf16 copy of c
__device__ float g_x2f[NN * FF];               // fp32 sum_t x^2
__device__ float g_c2f[KK * FF];
__device__ float g_dist[NN * KK];
__device__ float g_qpart[GRID * KK];
__device__ float g_lossb[GRID];
__device__ int g_c0, g_f0, g_c1, g_f1, g_c2, g_f2, g_c3;  // zero-init sync

__device__ __forceinline__ u32 hfma2b(u32 a, u32 b, u32 c) {
    u32 d;
    asm("fma.rn.bf16x2 %0, %1, %2, %3;" : "=r"(d) : "r"(a), "r"(b), "r"(c));
    return d;
}
__device__ __forceinline__ u32 f2b2(float a, float b) {
    __nv_bfloat162 h = __floats2bfloat162_rn(a, b);
    return *(u32*)&h;
}
__device__ __forceinline__ float2 b22f(u32 v) {
    return __bfloat1622float2(*(__nv_bfloat162*)&v);
}
__device__ __forceinline__ float fsqrt_approx(float x) {
    float r;
    asm("sqrt.approx.f32 %0, %1;" : "=f"(r) : "f"(x));
    return r;
}
__device__ __forceinline__ void bar_group(int id) {
    asm volatile("bar.sync %0, 64;" :: "r"(id) : "memory");
}
__device__ __forceinline__ void cp16(u32 s, const float4* g) {
    asm volatile("cp.async.cg.shared.global [%0], [%1], 16;" :: "r"(s), "l"(g));
}
__device__ __forceinline__ void cp_commit() {
    asm volatile("cp.async.commit_group;" ::: "memory");
}
template <int N>
__device__ __forceinline__ void cp_wait() {
    asm volatile("cp.async.wait_group %0;" :: "n"(N) : "memory");
}

// device-wide barrier: all GRID blocks co-resident (128 blocks, 1/SM)
__device__ __forceinline__ void gsync(int* cnt, int* flag) {
    __syncthreads();
    if (threadIdx.x == 0) {
        __threadfence();
        if (atomicAdd(cnt, 1) == GRID - 1) {
            atomicExch(flag, 1);
        } else {
            while (atomicAdd(flag, 0) == 0) { __nanosleep(32); }
        }
    }
    __syncthreads();
}

extern __shared__ float4 smemdyn[];

__global__ void __launch_bounds__(NTHR, 1)
soft_kmeans_mega(const float* __restrict__ x, const float* __restrict__ c,
                 float* __restrict__ out, int out_size) {
    const int tid = threadIdx.x;
    const int b   = blockIdx.x;

    // ========== Phase 0: convert to bf16 + fp32 x2/c2 ==========
    {
        float4* s4 = (float4*)smemdyn;
        // x: block b converts rows 2b, 2b+1 (each row = 2048 float4)
        const int half = tid >> 7, ht = tid & 127;
        const int f4x = ht & 15, tgx = ht >> 4;        // 128 ≡ 0 mod 16 -> f4 const
        const int r = 2 * b + half;
        const float4* src = (const float4*)x + (size_t)r * 2048;
        uint2* dst = (uint2*)g_xb + (size_t)r * 2048;
        float4 sq = make_float4(0.f, 0.f, 0.f, 0.f);
#pragma unroll
        for (int i = 0; i < 16; i++) {
            float4 v = src[ht + i * 128];
            sq.x = fmaf(v.x, v.x, sq.x); sq.y = fmaf(v.y, v.y, sq.y);
            sq.z = fmaf(v.z, v.z, sq.z); sq.w = fmaf(v.w, v.w, sq.w);
            uint2 w; w.x = f2b2(v.x, v.y); w.y = f2b2(v.z, v.w);
            dst[ht + i * 128] = w;
        }
        s4[half * 128 + tgx * 16 + f4x] = sq;
        __syncthreads();
        if (tgx == 0) {
            float4 tot = s4[half * 128 + f4x];
#pragma unroll
            for (int g2 = 1; g2 < 8; g2++) {
                float4 v = s4[half * 128 + g2 * 16 + f4x];
                tot.x += v.x; tot.y += v.y; tot.z += v.z; tot.w += v.w;
            }
            ((float4*)g_x2f)[r * 16 + f4x] = tot;
        }
        __syncthreads();
        // c: blocks 0..63 each convert row b (2048 float4, 256 threads)
        const int cf4 = tid & 15, ctg = tid >> 4;      // 256 ≡ 0 mod 16
        float4 sqc = make_float4(0.f, 0.f, 0.f, 0.f);
        if (b < 64) {
            const float4* csrc = (const float4*)c + (size_t)b * 2048;
            uint2* cdst = (uint2*)g_cb + (size_t)b * 2048;
#pragma unroll
            for (int i = 0; i < 8; i++) {
                float4 v = csrc[tid + i * 256];
                sqc.x = fmaf(v.x, v.x, sqc.x); sqc.y = fmaf(v.y, v.y, sqc.y);
                sqc.z = fmaf(v.z, v.z, sqc.z); sqc.w = fmaf(v.w, v.w, sqc.w);
                uint2 w; w.x = f2b2(v.x, v.y); w.y = f2b2(v.z, v.w);
                cdst[tid + i * 256] = w;
            }
        }
        s4[tid] = sqc;                      // [ctg][cf4]
        __syncthreads();
        if (b < 64 && ctg == 0) {
            float4 tot = s4[cf4];
#pragma unroll
            for (int g2 = 1; g2 < 16; g2++) {
                float4 v = s4[g2 * 16 + cf4];
                tot.x += v.x; tot.y += v.y; tot.z += v.z; tot.w += v.w;
            }
            ((float4*)g_c2f)[b * 16 + cf4] = tot;
        }
    }

    gsync(&g_c0, &g_f0);   // bf16 copies + x2/c2 ready

    // ===== Phase 1: distance tile (8n x 16k), 4 T-quarter groups ==========
    const int g  = tid >> 6;               // T-group 0..3 (32 t's each)
    const int wt = tid & 63;
    {
        const int fg  = wt & 7;            // 8 granules of 8 bf16 f's
        const int pos = wt >> 3;           // 0..7
        const int ni  = pos & 1;           // 2 n-subtiles of 4
        const int ki  = pos >> 1;          // 4 k-subtiles of 4
        const int n0  = (b >> 2) * TN;
        const int k0  = (b & 3) * TK;

        const float4* __restrict__ xgb = (const float4*)g_xb;  // granule=8 bf16
        const float4* __restrict__ cgb = (const float4*)g_cb;

        const u32 base_s = (u32)__cvta_generic_to_shared(smemdyn);
        const u32 g_s    = base_s + g * 2 * STAGE_B;

        u32 acc[4][4][4];                  // 4n x 4k x 4 bf16x2 (8 f's)
#pragma unroll
        for (int i = 0; i < 4; i++)
#pragma unroll
            for (int j = 0; j < 4; j++)
#pragma unroll
                for (int m = 0; m < 4; m++) acc[i][j][m] = 0u;

        auto issue_chunk = [&](int ch, int st) {
            const int t0 = g * 32 + ch * 4;
            const u32 xs_s = g_s + st * STAGE_B;
            const u32 cs_s = xs_s + 4096;
            // x: 8n*4t*8fg = 256 granules, 4/thread
#pragma unroll
            for (int i = 0; i < 4; i++) {
                int idx = wt + i * 64;
                int fgi = idx & 7, tt = (idx >> 3) & 3, nn = idx >> 5;
                cp16(xs_s + idx * 16,
                     xgb + ((n0 + nn) * TT + t0 + tt) * 8 + fgi);
            }
            // c: 16k*4t*8fg = 512 granules, 8/thread
#pragma unroll
            for (int i = 0; i < 8; i++) {
                int idx = wt + i * 64;
                int fgi = idx & 7, tt = (idx >> 3) & 3, kk = idx >> 5;
                cp16(cs_s + idx * 16,
                     cgb + ((k0 + kk) * TT + t0 + tt) * 8 + fgi);
            }
            cp_commit();
        };

        issue_chunk(0, 0);

#pragma unroll 2
        for (int ch = 0; ch < 8; ch++) {
            const int st = ch & 1;
            bar_group(1 + g);
            if (ch < 7) { issue_chunk(ch + 1, st ^ 1); cp_wait<1>(); }
            else        { cp_wait<0>(); }
            bar_group(1 + g);

            const uint4* xs4 = (const uint4*)((const char*)smemdyn + (g * 2 + st) * STAGE_B);
            const uint4* cs4 = xs4 + 256;
#pragma unroll
            for (int tt = 0; tt < 4; tt++) {
                uint4 xv[4], cv[4];
#pragma unroll
                for (int i = 0; i < 4; i++)
                    xv[i] = xs4[((ni * 4 + i) * 4 + tt) * 8 + fg];
#pragma unroll
                for (int j = 0; j < 4; j++)
                    cv[j] = cs4[((ki * 4 + j) * 4 + tt) * 8 + fg];
#pragma unroll
                for (int i = 0; i < 4; i++) {
                    const u32* xp = (const u32*)&xv[i];
#pragma unroll
                    for (int j = 0; j < 4; j++) {
                        const u32* cp = (const u32*)&cv[j];
                        acc[i][j][0] = hfma2b(xp[0], cp[0], acc[i][j][0]);
                        acc[i][j][1] = hfma2b(xp[1], cp[1], acc[i][j][1]);
                        acc[i][j][2] = hfma2b(xp[2], cp[2], acc[i][j][2]);
                        acc[i][j][3] = hfma2b(xp[3], cp[3], acc[i][j][3]);
                    }
                }
            }
        }

        // -------- combine 4 T-group partials (groups 1-3 -> smem) ----------
        u32* sall = (u32*)smemdyn;         // 3*16*4*64 = 12288 u32 = 48KB
        __syncthreads();
        if (g > 0) {
#pragma unroll
            for (int i = 0; i < 4; i++)
#pragma unroll
                for (int j = 0; j < 4; j++)
#pragma unroll
                    for (int m = 0; m < 4; m++)
                        sall[(((g - 1) * 16 + i * 4 + j) * 4 + m) * 64 + wt] = acc[i][j][m];
        }
        __syncthreads();
        if (g == 0) {
            // preload fp32 x2/c2 for this thread's 4 n's / 4 k's, 8 f's each
            float x2r[4][8], c2r[4][8];
#pragma unroll
            for (int i = 0; i < 4; i++) {
                const float4* p = (const float4*)(g_x2f + (n0 + ni * 4 + i) * FF + fg * 8);
                float4 a = p[0], d = p[1];
                x2r[i][0] = a.x; x2r[i][1] = a.y; x2r[i][2] = a.z; x2r[i][3] = a.w;
                x2r[i][4] = d.x; x2r[i][5] = d.y; x2r[i][6] = d.z; x2r[i][7] = d.w;
            }
#pragma unroll
            for (int j = 0; j < 4; j++) {
                const float4* p = (const float4*)(g_c2f + (k0 + ki * 4 + j) * FF + fg * 8);
                float4 a = p[0], d = p[1];
                c2r[j][0] = a.x; c2r[j][1] = a.y; c2r[j][2] = a.z; c2r[j][3] = a.w;
                c2r[j][4] = d.x; c2r[j][5] = d.y; c2r[j][6] = d.z; c2r[j][7] = d.w;
            }
#pragma unroll
            for (int i = 0; i < 4; i++) {
#pragma unroll
                for (int j = 0; j < 4; j++) {
                    float sf[8];
#pragma unroll
                    for (int m = 0; m < 4; m++) {
                        float2 v = b22f(acc[i][j][m]);
                        sf[2 * m] = v.x; sf[2 * m + 1] = v.y;
                    }
#pragma unroll
                    for (int gg = 0; gg < 3; gg++)
#pragma unroll
                        for (int m = 0; m < 4; m++) {
                            float2 v = b22f(sall[((gg * 16 + i * 4 + j) * 4 + m) * 64 + wt]);
                            sf[2 * m] += v.x; sf[2 * m + 1] += v.y;
                        }
                    float part = 0.0f;
#pragma unroll
                    for (int ff = 0; ff < 8; ff++) {
                        float d2 = fmaxf(x2r[i][ff] + c2r[j][ff] - 2.0f * sf[ff], 0.0f);
                        part += fsqrt_approx(d2);
                    }
#pragma unroll
                    for (int off = 4; off; off >>= 1)
                        part += __shfl_down_sync(0xffffffffu, part, off, 8);
                    if (fg == 0)
                        g_dist[(n0 + ni * 4 + i) * KK + (k0 + ki * 4 + j)] = part;
                }
            }
        }
    }

    gsync(&g_c1, &g_f1);   // g_dist complete everywhere

    float* s_tmp  = (float*)smemdyn;       // 256 floats
    float* s_red  = (float*)smemdyn + 256; // 8 floats
    int*   s_last = (int*)((float*)smemdyn + 270);

    // ================= Phase 2: q = softmax_k(1/(1+d^2)), rows 2b,2b+1 =====
    const int rloc = (tid >> 6) & 1;
    const int k    = tid & 63;
    const int n    = b * 2 + rloc;
    const int w    = tid >> 5;
    const int lane = tid & 31;
    const bool act = tid < 128;

    float q = 0.0f, e = 0.0f;
    if (act) {
        float d  = g_dist[n * KK + k];
        float q1 = 1.0f / (1.0f + d * d);   // alpha=1 -> exponent 1
        float m = q1;
#pragma unroll
        for (int o = 16; o; o >>= 1) m = fmaxf(m, __shfl_xor_sync(0xffffffffu, m, o));
        if (lane == 0) s_red[w] = m;
        e = q1;
    }
    __syncthreads();
    if (act) {
        float m = fmaxf(s_red[rloc * 2], s_red[rloc * 2 + 1]);
        e = expf(e - m);
        float s = e;
#pragma unroll
        for (int o = 16; o; o >>= 1) s += __shfl_xor_sync(0xffffffffu, s, o);
        if (lane == 0) s_red[4 + w] = s;
    }
    __syncthreads();
    if (act) {
        float s = s_red[4 + rloc * 2] + s_red[4 + rloc * 2 + 1];
        q = e / s;
        out[n * KK + k] = q;
        s_tmp[tid] = q;
    }
    __syncthreads();
    if (tid < 64) g_qpart[b * KK + tid] = s_tmp[tid] + s_tmp[tid + 64];

    gsync(&g_c2, &g_f2);   // all qpart written

    // ================= Phase 3: qsum, p, loss =================
    {
        const int quarter = tid >> 6;
        const int kq = tid & 63;
        float part = 0.0f;
#pragma unroll 8
        for (int bb = 0; bb < 32; bb++)
            part += g_qpart[(quarter * 32 + bb) * KK + kq];
        s_tmp[tid] = part;
        __syncthreads();
        float t = 0.0f;
        if (act) {
            float qsum = s_tmp[k] + s_tmp[64 + k] + s_tmp[128 + k] + s_tmp[192 + k];
            t = (q * q) / qsum;
            float m = t;
#pragma unroll
            for (int o = 16; o; o >>= 1) m = fmaxf(m, __shfl_xor_sync(0xffffffffu, m, o));
            if (lane == 0) s_red[w] = m;
        }
        __syncthreads();
        if (act) {
            float m = fmaxf(s_red[rloc * 2], s_red[rloc * 2 + 1]);
            e = expf(t - m);
            float s = e;
#pragma unroll
            for (int o = 16; o; o >>= 1) s += __shfl_xor_sync(0xffffffffu, s, o);
            if (lane == 0) s_red[4 + w] = s;
        }
        __syncthreads();
        if (act) {
            float s = s_red[4 + rloc * 2] + s_red[4 + rloc * 2 + 1];
            float p = e / s;
            float term = q * (logf(q) - p);
#pragma unroll
            for (int o = 16; o; o >>= 1) term += __shfl_xor_sync(0xffffffffu, term, o);
            if (lane == 0) s_red[w] = term;
        }
        __syncthreads();
        if (tid == 0)
            g_lossb[b] = s_red[0] + s_red[1] + s_red[2] + s_red[3];
        __syncthreads();
    }

    // ================= Phase 4: last block finalizes loss, resets sync =====
    if (tid == 0) {
        __threadfence();
        int old = atomicAdd(&g_c3, 1);
        *s_last = (old == GRID - 1) ? 1 : 0;
    }
    __syncthreads();
    if (*s_last) {
        if (tid < 128) s_tmp[tid] = g_lossb[tid];
        __syncthreads();
#pragma unroll
        for (int o = 64; o; o >>= 1) {
            if (tid < o) s_tmp[tid] += s_tmp[tid + o];
            __syncthreads();
        }
        if (tid == 0) {
            if (out_size > NN * KK) out[NN * KK] = s_tmp[0] / (float)NN;
            atomicExch(&g_c0, 0); atomicExch(&g_f0, 0);
            atomicExch(&g_c1, 0); atomicExch(&g_f1, 0);
            atomicExch(&g_c2, 0); atomicExch(&g_f2, 0);
            atomicExch(&g_c3, 0);
            __threadfence();
        }
    }
}

extern "C" void kernel_launch(void* const* d_in, const int* in_sizes, int n_in,
                              void* d_out, int out_size) {
    const float* x = (const float*)d_in[0];   // inputs  (N,T,F)
    const float* c = (const float*)d_in[1];   // clusters(K,T,F)
    float* out = (float*)d_out;

    cudaFuncSetAttribute(soft_kmeans_mega,
                         cudaFuncAttributeMaxDynamicSharedMemorySize, SMEM_BYTES);
    soft_kmeans_mega<<<GRID, NTHR, SMEM_BYTES>>>(x, c, out, out_size);
}

// round 16
// speedup vs baseline: 1.2889x; 1.1083x over previous
#include <cuda_runtime.h>
#include <cuda_bf16.h>
#include <cstdint>

#define NN 256
#define KK 64
#define TT 128
#define FF 64
#define TN 8
#define TK 16
#define GRID 128
#define NTHR 512
#define STAGE_B 12288                     // bytes/stage: x 4KB + c 8KB (bf16)
#define SMEM_BYTES (4 * 2 * STAGE_B)      // 4 T-groups x 2 stages = 96KB

typedef unsigned long long u64;
typedef unsigned int u32;

// ---------------- scratch (no allocations allowed) ----------------
__device__ __nv_bfloat16 g_xb[NN * TT * FF];   // 4MB bf16 copy of x
__device__ __nv_bfloat16 g_cb[KK * TT * FF];   // 1MB bf16 copy of c
__device__ float g_x2f[NN * FF];               // fp32 sum_t x^2
__device__ float g_c2f[KK * FF];
__device__ float g_dist[NN * KK];
__device__ float g_qpart[GRID * KK];
__device__ float g_lossb[GRID];
__device__ int g_c0, g_f0, g_c1, g_f1, g_c2, g_f2, g_c3;  // zero-init sync

__device__ __forceinline__ u32 hfma2b(u32 a, u32 b, u32 c) {
    u32 d;
    asm("fma.rn.bf16x2 %0, %1, %2, %3;" : "=r"(d) : "r"(a), "r"(b), "r"(c));
    return d;
}
__device__ __forceinline__ u32 f2b2(float a, float b) {
    __nv_bfloat162 h = __floats2bfloat162_rn(a, b);
    return *(u32*)&h;
}
__device__ __forceinline__ float2 b22f(u32 v) {
    return __bfloat1622float2(*(__nv_bfloat162*)&v);
}
__device__ __forceinline__ float fsqrt_approx(float x) {
    float r;
    asm("sqrt.approx.f32 %0, %1;" : "=f"(r) : "f"(x));
    return r;
}
__device__ __forceinline__ void bar_group(int id) {
    asm volatile("bar.sync %0, 128;" :: "r"(id) : "memory");
}
__device__ __forceinline__ void cp16(u32 s, const float4* g) {
    asm volatile("cp.async.cg.shared.global [%0], [%1], 16;" :: "r"(s), "l"(g));
}
__device__ __forceinline__ void cp_commit() {
    asm volatile("cp.async.commit_group;" ::: "memory");
}
template <int N>
__device__ __forceinline__ void cp_wait() {
    asm volatile("cp.async.wait_group %0;" :: "n"(N) : "memory");
}

// device-wide barrier: all GRID blocks co-resident (128 blocks, 1/SM)
__device__ __forceinline__ void gsync(int* cnt, int* flag) {
    __syncthreads();
    if (threadIdx.x == 0) {
        __threadfence();
        if (atomicAdd(cnt, 1) == GRID - 1) {
            atomicExch(flag, 1);
        } else {
            while (atomicAdd(flag, 0) == 0) { __nanosleep(32); }
        }
    }
    __syncthreads();
}

extern __shared__ float4 smemdyn[];

__global__ void __launch_bounds__(NTHR, 1)
soft_kmeans_mega(const float* __restrict__ x, const float* __restrict__ c,
                 float* __restrict__ out, int out_size) {
    const int tid = threadIdx.x;
    const int b   = blockIdx.x;

    // ========== Phase 0: convert to bf16 + fp32 x2/c2 (512 threads) ==========
    {
        float4* s4 = (float4*)smemdyn;
        // x: block b converts rows 2b, 2b+1 (each row = 2048 float4)
        const int half = tid >> 8, ht = tid & 255;
        const int f4x = ht & 15, tgx = ht >> 4;        // 256 ≡ 0 mod 16
        const int r = 2 * b + half;
        const float4* src = (const float4*)x + (size_t)r * 2048;
        uint2* dst = (uint2*)g_xb + (size_t)r * 2048;
        float4 sq = make_float4(0.f, 0.f, 0.f, 0.f);
#pragma unroll
        for (int i = 0; i < 8; i++) {
            float4 v = src[ht + i * 256];
            sq.x = fmaf(v.x, v.x, sq.x); sq.y = fmaf(v.y, v.y, sq.y);
            sq.z = fmaf(v.z, v.z, sq.z); sq.w = fmaf(v.w, v.w, sq.w);
            uint2 w; w.x = f2b2(v.x, v.y); w.y = f2b2(v.z, v.w);
            dst[ht + i * 256] = w;
        }
        s4[half * 256 + tgx * 16 + f4x] = sq;
        __syncthreads();
        if (tgx == 0) {
            float4 tot = s4[half * 256 + f4x];
#pragma unroll
            for (int g2 = 1; g2 < 16; g2++) {
                float4 v = s4[half * 256 + g2 * 16 + f4x];
                tot.x += v.x; tot.y += v.y; tot.z += v.z; tot.w += v.w;
            }
            ((float4*)g_x2f)[r * 16 + f4x] = tot;
        }
        __syncthreads();
        // c: blocks 0..63 each convert row b (2048 float4, 512 threads)
        const int cf4 = tid & 15, ctg = tid >> 4;      // 512 ≡ 0 mod 16
        float4 sqc = make_float4(0.f, 0.f, 0.f, 0.f);
        if (b < 64) {
            const float4* csrc = (const float4*)c + (size_t)b * 2048;
            uint2* cdst = (uint2*)g_cb + (size_t)b * 2048;
#pragma unroll
            for (int i = 0; i < 4; i++) {
                float4 v = csrc[tid + i * 512];
                sqc.x = fmaf(v.x, v.x, sqc.x); sqc.y = fmaf(v.y, v.y, sqc.y);
                sqc.z = fmaf(v.z, v.z, sqc.z); sqc.w = fmaf(v.w, v.w, sqc.w);
                uint2 w; w.x = f2b2(v.x, v.y); w.y = f2b2(v.z, v.w);
                cdst[tid + i * 512] = w;
            }
        }
        s4[tid] = sqc;                      // [ctg][cf4]
        __syncthreads();
        if (b < 64 && ctg == 0) {
            float4 tot = s4[cf4];
#pragma unroll
            for (int g2 = 1; g2 < 32; g2++) {
                float4 v = s4[g2 * 16 + cf4];
                tot.x += v.x; tot.y += v.y; tot.z += v.z; tot.w += v.w;
            }
            ((float4*)g_c2f)[b * 16 + cf4] = tot;
        }
    }

    gsync(&g_c0, &g_f0);   // bf16 copies + x2/c2 ready

    // ===== Phase 1: distance tile (8n x 16k), 4 T-quarter groups x 128 =====
    const int g  = tid >> 7;               // T-group 0..3 (32 t's each)
    const int wt = tid & 127;
    {
        const int fg  = wt & 15;           // 16 granules of 4 bf16 f's (8B)
        const int pos = wt >> 4;           // 0..7
        const int ni  = pos & 1;           // 2 n-subtiles of 4
        const int ki  = pos >> 1;          // 4 k-subtiles of 4
        const int n0  = (b >> 2) * TN;
        const int k0  = (b & 3) * TK;

        const float4* __restrict__ xgb = (const float4*)g_xb;  // 16B = 8 bf16
        const float4* __restrict__ cgb = (const float4*)g_cb;

        const u32 base_s = (u32)__cvta_generic_to_shared(smemdyn);
        const u32 g_s    = base_s + g * 2 * STAGE_B;

        u32 acc[4][4][2];                  // 4n x 4k x 2 bf16x2 (4 f's)
#pragma unroll
        for (int i = 0; i < 4; i++)
#pragma unroll
            for (int j = 0; j < 4; j++) { acc[i][j][0] = 0u; acc[i][j][1] = 0u; }

        auto issue_chunk = [&](int ch, int st) {
            const int t0 = g * 32 + ch * 4;
            const u32 xs_s = g_s + st * STAGE_B;
            const u32 cs_s = xs_s + 4096;
            // x: 8n*4t*8 16B-units = 256, 2/thread
#pragma unroll
            for (int i = 0; i < 2; i++) {
                int idx = wt + i * 128;
                int fgi = idx & 7, tt = (idx >> 3) & 3, nn = idx >> 5;
                cp16(xs_s + idx * 16,
                     xgb + ((n0 + nn) * TT + t0 + tt) * 8 + fgi);
            }
            // c: 16k*4t*8 = 512, 4/thread
#pragma unroll
            for (int i = 0; i < 4; i++) {
                int idx = wt + i * 128;
                int fgi = idx & 7, tt = (idx >> 3) & 3, kk = idx >> 5;
                cp16(cs_s + idx * 16,
                     cgb + ((k0 + kk) * TT + t0 + tt) * 8 + fgi);
            }
            cp_commit();
        };

        issue_chunk(0, 0);

#pragma unroll 2
        for (int ch = 0; ch < 8; ch++) {
            const int st = ch & 1;
            bar_group(1 + g);
            if (ch < 7) { issue_chunk(ch + 1, st ^ 1); cp_wait<1>(); }
            else        { cp_wait<0>(); }
            bar_group(1 + g);

            const uint2* xs2 = (const uint2*)((const char*)smemdyn + (g * 2 + st) * STAGE_B);
            const uint2* cs2 = xs2 + 512;  // +4KB
#pragma unroll
            for (int tt = 0; tt < 4; tt++) {
                uint2 xv[4], cv[4];
#pragma unroll
                for (int i = 0; i < 4; i++)
                    xv[i] = xs2[((ni * 4 + i) * 4 + tt) * 16 + fg];
#pragma unroll
                for (int j = 0; j < 4; j++)
                    cv[j] = cs2[((ki * 4 + j) * 4 + tt) * 16 + fg];
#pragma unroll
                for (int i = 0; i < 4; i++)
#pragma unroll
                    for (int j = 0; j < 4; j++) {
                        acc[i][j][0] = hfma2b(xv[i].x, cv[j].x, acc[i][j][0]);
                        acc[i][j][1] = hfma2b(xv[i].y, cv[j].y, acc[i][j][1]);
                    }
            }
        }

        // -------- combine 4 T-group partials (groups 1-3 -> smem) ----------
        u32* sall = (u32*)smemdyn;         // 3*32*128 = 12288 u32 = 48KB
        __syncthreads();
        if (g > 0) {
#pragma unroll
            for (int i = 0; i < 4; i++)
#pragma unroll
                for (int j = 0; j < 4; j++)
#pragma unroll
                    for (int m = 0; m < 2; m++)
                        sall[(((g - 1) * 16 + i * 4 + j) * 2 + m) * 128 + wt] = acc[i][j][m];
        }
        __syncthreads();
        if (g == 0) {
            // fp32 x2/c2 for this thread's 4 n's / 4 k's, 4 f's each
            float x2r[4][4], c2r[4][4];
#pragma unroll
            for (int i = 0; i < 4; i++) {
                float4 a = ((const float4*)(g_x2f + (n0 + ni * 4 + i) * FF))[fg];
                x2r[i][0] = a.x; x2r[i][1] = a.y; x2r[i][2] = a.z; x2r[i][3] = a.w;
            }
#pragma unroll
            for (int j = 0; j < 4; j++) {
                float4 a = ((const float4*)(g_c2f + (k0 + ki * 4 + j) * FF))[fg];
                c2r[j][0] = a.x; c2r[j][1] = a.y; c2r[j][2] = a.z; c2r[j][3] = a.w;
            }
#pragma unroll
            for (int i = 0; i < 4; i++) {
#pragma unroll
                for (int j = 0; j < 4; j++) {
                    float sf[4];
                    float2 v0 = b22f(acc[i][j][0]), v1 = b22f(acc[i][j][1]);
                    sf[0] = v0.x; sf[1] = v0.y; sf[2] = v1.x; sf[3] = v1.y;
#pragma unroll
                    for (int gg = 0; gg < 3; gg++) {
                        float2 w0 = b22f(sall[((gg * 16 + i * 4 + j) * 2 + 0) * 128 + wt]);
                        float2 w1 = b22f(sall[((gg * 16 + i * 4 + j) * 2 + 1) * 128 + wt]);
                        sf[0] += w0.x; sf[1] += w0.y; sf[2] += w1.x; sf[3] += w1.y;
                    }
                    float part = 0.0f;
#pragma unroll
                    for (int ff = 0; ff < 4; ff++) {
                        float d2 = fmaxf(x2r[i][ff] + c2r[j][ff] - 2.0f * sf[ff], 0.0f);
                        part += fsqrt_approx(d2);
                    }
#pragma unroll
                    for (int off = 8; off; off >>= 1)
                        part += __shfl_down_sync(0xffffffffu, part, off, 16);
                    if (fg == 0)
                        g_dist[(n0 + ni * 4 + i) * KK + (k0 + ki * 4 + j)] = part;
                }
            }
        }
    }

    gsync(&g_c1, &g_f1);   // g_dist complete everywhere

    float* s_tmp  = (float*)smemdyn;       // 512 floats
    float* s_red  = (float*)smemdyn + 512; // 8 floats
    int*   s_last = (int*)((float*)smemdyn + 526);

    // ================= Phase 2: q = softmax_k(1/(1+d^2)), rows 2b,2b+1 =====
    const int rloc = (tid >> 6) & 1;
    const int k    = tid & 63;
    const int n    = b * 2 + rloc;
    const int w    = tid >> 5;
    const int lane = tid & 31;
    const bool act = tid < 128;

    float q = 0.0f, e = 0.0f;
    if (act) {
        float d  = g_dist[n * KK + k];
        float q1 = 1.0f / (1.0f + d * d);   // alpha=1 -> exponent 1
        float m = q1;
#pragma unroll
        for (int o = 16; o; o >>= 1) m = fmaxf(m, __shfl_xor_sync(0xffffffffu, m, o));
        if (lane == 0) s_red[w] = m;
        e = q1;
    }
    __syncthreads();
    if (act) {
        float m = fmaxf(s_red[rloc * 2], s_red[rloc * 2 + 1]);
        e = expf(e - m);
        float s = e;
#pragma unroll
        for (int o = 16; o; o >>= 1) s += __shfl_xor_sync(0xffffffffu, s, o);
        if (lane == 0) s_red[4 + w] = s;
    }
    __syncthreads();
    if (act) {
        float s = s_red[4 + rloc * 2] + s_red[4 + rloc * 2 + 1];
        q = e / s;
        out[n * KK + k] = q;
        s_tmp[tid] = q;
    }
    __syncthreads();
    if (tid < 64) g_qpart[b * KK + tid] = s_tmp[tid] + s_tmp[tid + 64];

    gsync(&g_c2, &g_f2);   // all qpart written

    // ================= Phase 3: qsum, p, loss =================
    {
        const int eighth = tid >> 6;        // 0..7
        const int kq = tid & 63;
        float part = 0.0f;
#pragma unroll 8
        for (int bb = 0; bb < 16; bb++)
            part += g_qpart[(eighth * 16 + bb) * KK + kq];
        s_tmp[tid] = part;
        __syncthreads();
        float t = 0.0f;
        if (act) {
            float qsum = 0.0f;
#pragma unroll
            for (int m8 = 0; m8 < 8; m8++) qsum += s_tmp[m8 * 64 + k];
            t = (q * q) / qsum;
            float m = t;
#pragma unroll
            for (int o = 16; o; o >>= 1) m = fmaxf(m, __shfl_xor_sync(0xffffffffu, m, o));
            if (lane == 0) s_red[w] = m;
        }
        __syncthreads();
        if (act) {
            float m = fmaxf(s_red[rloc * 2], s_red[rloc * 2 + 1]);
            e = expf(t - m);
            float s = e;
#pragma unroll
            for (int o = 16; o; o >>= 1) s += __shfl_xor_sync(0xffffffffu, s, o);
            if (lane == 0) s_red[4 + w] = s;
        }
        __syncthreads();
        if (act) {
            float s = s_red[4 + rloc * 2] + s_red[4 + rloc * 2 + 1];
            float p = e / s;
            float term = q * (logf(q) - p);
#pragma unroll
            for (int o = 16; o; o >>= 1) term += __shfl_xor_sync(0xffffffffu, term, o);
            if (lane == 0) s_red[w] = term;
        }
        __syncthreads();
        if (tid == 0)
            g_lossb[b] = s_red[0] + s_red[1] + s_red[2] + s_red[3];
        __syncthreads();
    }

    // ================= Phase 4: last block finalizes loss, resets sync =====
    if (tid == 0) {
        __threadfence();
        int old = atomicAdd(&g_c3, 1);
        *s_last = (old == GRID - 1) ? 1 : 0;
    }
    __syncthreads();
    if (*s_last) {
        if (tid < 128) s_tmp[tid] = g_lossb[tid];
        __syncthreads();
#pragma unroll
        for (int o = 64; o; o >>= 1) {
            if (tid < o) s_tmp[tid] += s_tmp[tid + o];
            __syncthreads();
        }
        if (tid == 0) {
            if (out_size > NN * KK) out[NN * KK] = s_tmp[0] / (float)NN;
            atomicExch(&g_c0, 0); atomicExch(&g_f0, 0);
            atomicExch(&g_c1, 0); atomicExch(&g_f1, 0);
            atomicExch(&g_c2, 0); atomicExch(&g_f2, 0);
            atomicExch(&g_c3, 0);
            __threadfence();
        }
    }
}

extern "C" void kernel_launch(void* const* d_in, const int* in_sizes, int n_in,
                              void* d_out, int out_size) {
    const float* x = (const float*)d_in[0];   // inputs  (N,T,F)
    const float* c = (const float*)d_in[1];   // clusters(K,T,F)
    float* out = (float*)d_out;

    cudaFuncSetAttribute(soft_kmeans_mega,
                         cudaFuncAttributeMaxDynamicSharedMemorySize, SMEM_BYTES);
    soft_kmeans_mega<<<GRID, NTHR, SMEM_BYTES>>>(x, c, out, out_size);
}